// round 1
// baseline (speedup 1.0000x reference)
#include <cuda_runtime.h>
#include <cuda_bf16.h>

#define SEQ    2048
#define BATCH  64
#define D      256
#define CHUNKS 4
#define CHUNK_S (SEQ / CHUNKS)   // 512
#define HSIZE  4096
#define HMASK  (HSIZE - 1)
#define POOL_THREADS 256

// Per-(batch,chunk) partial pooled vectors. Each CTA writes its own slice fully,
// so no zero-init or atomics needed.
__device__ float g_partial[BATCH * CHUNKS * D];

__device__ __forceinline__ unsigned hash_tok(int tok) {
    return ((unsigned)tok * 2654435761u) & HMASK;
}

// Kernel 1: per (batch, seq-chunk) CTA.
//  - load full token row into smem
//  - build full-row TF histogram in a smem hash table
//  - compute tf*idf weights for this chunk
//  - gather-accumulate weighted embeddings for this chunk (float4 per thread)
__global__ __launch_bounds__(POOL_THREADS, 2)
void pool_kernel(const int* __restrict__ x,
                 const float* __restrict__ emb,
                 const float* __restrict__ idf) {
    __shared__ int   tok_sh[SEQ];       // 8 KB
    __shared__ int   hkey[HSIZE];       // 16 KB
    __shared__ int   hcnt[HSIZE];       // 16 KB
    __shared__ float w_sh[CHUNK_S];     // 2 KB
    __shared__ float4 red4[4][D / 4];   // 4 KB

    const int tid   = threadIdx.x;
    const int b     = blockIdx.x >> 2;   // batch
    const int chunk = blockIdx.x & 3;    // seq chunk

    // init hash table
    #pragma unroll
    for (int i = tid; i < HSIZE; i += POOL_THREADS) {
        hkey[i] = -1;
        hcnt[i] = 0;
    }
    // load token row (x is [SEQ, BATCH], stride BATCH per seq step)
    #pragma unroll
    for (int s = tid; s < SEQ; s += POOL_THREADS) {
        tok_sh[s] = x[s * BATCH + b];
    }
    __syncthreads();

    // insert all non-pad tokens into hash table (counts = tf)
    #pragma unroll
    for (int s = tid; s < SEQ; s += POOL_THREADS) {
        int tok = tok_sh[s];
        if (tok == 0) continue;
        unsigned h = hash_tok(tok);
        while (true) {
            int prev = atomicCAS(&hkey[h], -1, tok);
            if (prev == -1 || prev == tok) {
                atomicAdd(&hcnt[h], 1);
                break;
            }
            h = (h + 1) & HMASK;
        }
    }
    __syncthreads();

    // compute weights w[s] = tf(tok)*idf(tok) (0 for pad) for this chunk
    const int base = chunk * CHUNK_S;
    for (int i = tid; i < CHUNK_S; i += POOL_THREADS) {
        int tok = tok_sh[base + i];
        float w = 0.0f;
        if (tok != 0) {
            unsigned h = hash_tok(tok);
            while (hkey[h] != tok) h = (h + 1) & HMASK;
            w = (float)hcnt[h] * __ldg(&idf[tok]);
        }
        w_sh[i] = w;
    }
    __syncthreads();

    // gather: thread layout = (sg in [0,4), dq in [0,64))
    // thread accumulates d-range [4*dq, 4*dq+4) over positions s ≡ sg (mod 4)
    const int sg = tid >> 6;
    const int dq = tid & 63;

    float4 acc = make_float4(0.f, 0.f, 0.f, 0.f);
    #pragma unroll 4
    for (int s = sg; s < CHUNK_S; s += 4) {
        float w  = w_sh[s];
        int  tok = tok_sh[base + s];
        float4 v = __ldg(reinterpret_cast<const float4*>(emb + (size_t)tok * D) + dq);
        acc.x += w * v.x;
        acc.y += w * v.y;
        acc.z += w * v.z;
        acc.w += w * v.w;
    }
    red4[sg][dq] = acc;
    __syncthreads();

    // reduce the 4 sg-partials and store this CTA's partial pooled vector
    if (tid < D / 4) {
        float4 a = red4[0][tid];
        float4 c = red4[1][tid];
        float4 e = red4[2][tid];
        float4 f = red4[3][tid];
        float4 r = make_float4(a.x + c.x + e.x + f.x,
                               a.y + c.y + e.y + f.y,
                               a.z + c.z + e.z + f.z,
                               a.w + c.w + e.w + f.w);
        reinterpret_cast<float4*>(g_partial + ((size_t)b * CHUNKS + chunk) * D)[tid] = r;
    }
}

// Kernel 2: per-batch MLP + softmax. Warp-per-output dot products with
// coalesced weight reads + shuffle reduction.
__global__ __launch_bounds__(128, 8)
void mlp_kernel(const float* __restrict__ W1, const float* __restrict__ b1,
                const float* __restrict__ W2, const float* __restrict__ b2,
                const float* __restrict__ W3, const float* __restrict__ b3,
                float* __restrict__ out) {
    const int b    = blockIdx.x;
    const int tid  = threadIdx.x;
    const int lane = tid & 31;
    const int wrp  = tid >> 5;   // 4 warps

    __shared__ float pooled[D];
    __shared__ float h1[100];
    __shared__ float h2[150];
    __shared__ float z[2];

    // sum the 4 chunk partials
    for (int i = tid; i < D; i += 128) {
        const float* p = g_partial + (size_t)b * CHUNKS * D + i;
        pooled[i] = p[0] + p[D] + p[2 * D] + p[3 * D];
    }
    __syncthreads();

    // h1 = relu(pooled @ W1^T + b1), W1: [100, 256]
    for (int j = wrp; j < 100; j += 4) {
        float s = 0.f;
        #pragma unroll
        for (int d = lane; d < 256; d += 32) s += pooled[d] * W1[j * 256 + d];
        #pragma unroll
        for (int o = 16; o; o >>= 1) s += __shfl_xor_sync(0xffffffffu, s, o);
        if (lane == 0) h1[j] = fmaxf(s + b1[j], 0.f);
    }
    __syncthreads();

    // h2 = relu(h1 @ W2^T + b2), W2: [150, 100]
    for (int j = wrp; j < 150; j += 4) {
        float s = 0.f;
        for (int d = lane; d < 100; d += 32) s += h1[d] * W2[j * 100 + d];
        #pragma unroll
        for (int o = 16; o; o >>= 1) s += __shfl_xor_sync(0xffffffffu, s, o);
        if (lane == 0) h2[j] = fmaxf(s + b2[j], 0.f);
    }
    __syncthreads();

    // logits = h2 @ W3^T + b3, W3: [2, 150]
    if (wrp < 2) {
        float s = 0.f;
        for (int d = lane; d < 150; d += 32) s += h2[d] * W3[wrp * 150 + d];
        #pragma unroll
        for (int o = 16; o; o >>= 1) s += __shfl_xor_sync(0xffffffffu, s, o);
        if (lane == 0) z[wrp] = s + b3[wrp];
    }
    __syncthreads();

    if (tid == 0) {
        float m  = fmaxf(z[0], z[1]);
        float e0 = expf(z[0] - m);
        float e1 = expf(z[1] - m);
        float inv = 1.0f / (e0 + e1);
        out[b * 2 + 0] = e0 * inv;
        out[b * 2 + 1] = e1 * inv;
    }
}

extern "C" void kernel_launch(void* const* d_in, const int* in_sizes, int n_in,
                              void* d_out, int out_size) {
    const int*   x   = (const int*)  d_in[0];
    const float* emb = (const float*)d_in[1];
    const float* idf = (const float*)d_in[2];
    const float* W1  = (const float*)d_in[3];
    const float* b1  = (const float*)d_in[4];
    const float* W2  = (const float*)d_in[5];
    const float* b2  = (const float*)d_in[6];
    const float* W3  = (const float*)d_in[7];
    const float* b3  = (const float*)d_in[8];
    float* out = (float*)d_out;

    pool_kernel<<<BATCH * CHUNKS, POOL_THREADS>>>(x, emb, idf);
    mlp_kernel<<<BATCH, 128>>>(W1, b1, W2, b2, W3, b3, out);
}

// round 2
// speedup vs baseline: 1.7671x; 1.7671x over previous
#include <cuda_runtime.h>
#include <cuda_bf16.h>

#define SEQ    2048
#define BATCH  64
#define D      256
#define CHUNKS 4
#define CHUNK_S (SEQ / CHUNKS)   // 512
#define HSIZE  4096
#define HMASK  (HSIZE - 1)
#define POOL_THREADS 256

#define H1 100
#define H2 150

// Scratch (device globals — no allocations allowed)
__device__ float g_partial[BATCH * CHUNKS * D];
__device__ float g_pooled [BATCH * D];
__device__ float g_h1     [BATCH * H1];
__device__ float g_h2     [BATCH * H2];

__device__ __forceinline__ unsigned hash_tok(int tok) {
    return ((unsigned)tok * 2654435761u) & HMASK;
}

// ---------------------------------------------------------------------------
// Kernel 1: per (batch, seq-chunk) CTA — TF-IDF weighted embedding gather.
// ---------------------------------------------------------------------------
__global__ __launch_bounds__(POOL_THREADS, 2)
void pool_kernel(const int* __restrict__ x,
                 const float* __restrict__ emb,
                 const float* __restrict__ idf) {
    __shared__ int   tok_sh[SEQ];       // 8 KB
    __shared__ int   hkey[HSIZE];       // 16 KB
    __shared__ int   hcnt[HSIZE];       // 16 KB
    __shared__ float w_sh[CHUNK_S];     // 2 KB
    __shared__ float4 red4[4][D / 4];   // 4 KB

    const int tid   = threadIdx.x;
    const int b     = blockIdx.x >> 2;
    const int chunk = blockIdx.x & 3;

    #pragma unroll
    for (int i = tid; i < HSIZE; i += POOL_THREADS) {
        hkey[i] = -1;
        hcnt[i] = 0;
    }
    #pragma unroll
    for (int s = tid; s < SEQ; s += POOL_THREADS) {
        tok_sh[s] = x[s * BATCH + b];
    }
    __syncthreads();

    #pragma unroll
    for (int s = tid; s < SEQ; s += POOL_THREADS) {
        int tok = tok_sh[s];
        if (tok == 0) continue;
        unsigned h = hash_tok(tok);
        while (true) {
            int prev = atomicCAS(&hkey[h], -1, tok);
            if (prev == -1 || prev == tok) {
                atomicAdd(&hcnt[h], 1);
                break;
            }
            h = (h + 1) & HMASK;
        }
    }
    __syncthreads();

    const int base = chunk * CHUNK_S;
    for (int i = tid; i < CHUNK_S; i += POOL_THREADS) {
        int tok = tok_sh[base + i];
        float w = 0.0f;
        if (tok != 0) {
            unsigned h = hash_tok(tok);
            while (hkey[h] != tok) h = (h + 1) & HMASK;
            w = (float)hcnt[h] * __ldg(&idf[tok]);
        }
        w_sh[i] = w;
    }
    __syncthreads();

    const int sg = tid >> 6;
    const int dq = tid & 63;

    float4 acc = make_float4(0.f, 0.f, 0.f, 0.f);
    #pragma unroll 4
    for (int s = sg; s < CHUNK_S; s += 4) {
        float w  = w_sh[s];
        int  tok = tok_sh[base + s];
        float4 v = __ldg(reinterpret_cast<const float4*>(emb + (size_t)tok * D) + dq);
        acc.x += w * v.x;
        acc.y += w * v.y;
        acc.z += w * v.z;
        acc.w += w * v.w;
    }
    red4[sg][dq] = acc;
    __syncthreads();

    if (tid < D / 4) {
        float4 a = red4[0][tid];
        float4 c = red4[1][tid];
        float4 e = red4[2][tid];
        float4 f = red4[3][tid];
        float4 r = make_float4(a.x + c.x + e.x + f.x,
                               a.y + c.y + e.y + f.y,
                               a.z + c.z + e.z + f.z,
                               a.w + c.w + e.w + f.w);
        reinterpret_cast<float4*>(g_partial + ((size_t)b * CHUNKS + chunk) * D)[tid] = r;
    }
}

// ---------------------------------------------------------------------------
// Kernel 2: reduce the 4 chunk partials -> pooled [B, D]. 64 blocks x 64 thr.
// ---------------------------------------------------------------------------
__global__ __launch_bounds__(64)
void reduce_kernel() {
    const int b = blockIdx.x;
    const int i = threadIdx.x;   // float4 index within D
    const float4* p = reinterpret_cast<const float4*>(g_partial + (size_t)b * CHUNKS * D);
    float4 a = p[i];
    float4 c = p[i + D / 4];
    float4 e = p[i + 2 * (D / 4)];
    float4 f = p[i + 3 * (D / 4)];
    float4 r = make_float4(a.x + c.x + e.x + f.x,
                           a.y + c.y + e.y + f.y,
                           a.z + c.z + e.z + f.z,
                           a.w + c.w + e.w + f.w);
    reinterpret_cast<float4*>(g_pooled + (size_t)b * D)[i] = r;
}

// ---------------------------------------------------------------------------
// Kernel 3: layer1 — one warp per (b, j); 6400 warps total.
// h1[b,j] = relu(dot(pooled[b,:], W1[j,:]) + b1[j])
// ---------------------------------------------------------------------------
__global__ __launch_bounds__(256)
void l1_kernel(const float* __restrict__ W1, const float* __restrict__ b1) {
    const int lane = threadIdx.x & 31;
    const int pair = blockIdx.x * 8 + (threadIdx.x >> 5);
    const int b = pair / H1;
    const int j = pair % H1;

    const float* P = g_pooled + (size_t)b * D;
    const float* W = W1 + (size_t)j * D;
    float s = 0.f;
    #pragma unroll
    for (int d = lane; d < D; d += 32) s += P[d] * W[d];
    #pragma unroll
    for (int o = 16; o; o >>= 1) s += __shfl_xor_sync(0xffffffffu, s, o);
    if (lane == 0) g_h1[b * H1 + j] = fmaxf(s + b1[j], 0.f);
}

// ---------------------------------------------------------------------------
// Kernel 4: layer2 — one warp per (b, j); 9600 warps total.
// ---------------------------------------------------------------------------
__global__ __launch_bounds__(256)
void l2_kernel(const float* __restrict__ W2, const float* __restrict__ b2) {
    const int lane = threadIdx.x & 31;
    const int pair = blockIdx.x * 8 + (threadIdx.x >> 5);
    const int b = pair / H2;
    const int j = pair % H2;

    const float* Hv = g_h1 + (size_t)b * H1;
    const float* W  = W2 + (size_t)j * H1;
    float s = 0.f;
    for (int d = lane; d < H1; d += 32) s += Hv[d] * W[d];
    #pragma unroll
    for (int o = 16; o; o >>= 1) s += __shfl_xor_sync(0xffffffffu, s, o);
    if (lane == 0) g_h2[b * H2 + j] = fmaxf(s + b2[j], 0.f);
}

// ---------------------------------------------------------------------------
// Kernel 5: layer3 + softmax — one block per batch, one warp per logit.
// ---------------------------------------------------------------------------
__global__ __launch_bounds__(64)
void l3_kernel(const float* __restrict__ W3, const float* __restrict__ b3,
               float* __restrict__ out) {
    const int b    = blockIdx.x;
    const int lane = threadIdx.x & 31;
    const int wrp  = threadIdx.x >> 5;   // 0 or 1

    __shared__ float z[2];

    const float* Hv = g_h2 + (size_t)b * H2;
    const float* W  = W3 + (size_t)wrp * H2;
    float s = 0.f;
    for (int d = lane; d < H2; d += 32) s += Hv[d] * W[d];
    #pragma unroll
    for (int o = 16; o; o >>= 1) s += __shfl_xor_sync(0xffffffffu, s, o);
    if (lane == 0) z[wrp] = s + b3[wrp];
    __syncthreads();

    if (threadIdx.x == 0) {
        float m  = fmaxf(z[0], z[1]);
        float e0 = expf(z[0] - m);
        float e1 = expf(z[1] - m);
        float inv = 1.0f / (e0 + e1);
        out[b * 2 + 0] = e0 * inv;
        out[b * 2 + 1] = e1 * inv;
    }
}

extern "C" void kernel_launch(void* const* d_in, const int* in_sizes, int n_in,
                              void* d_out, int out_size) {
    const int*   x   = (const int*)  d_in[0];
    const float* emb = (const float*)d_in[1];
    const float* idf = (const float*)d_in[2];
    const float* W1  = (const float*)d_in[3];
    const float* b1  = (const float*)d_in[4];
    const float* W2  = (const float*)d_in[5];
    const float* b2  = (const float*)d_in[6];
    const float* W3  = (const float*)d_in[7];
    const float* b3  = (const float*)d_in[8];
    float* out = (float*)d_out;

    pool_kernel<<<BATCH * CHUNKS, POOL_THREADS>>>(x, emb, idf);
    reduce_kernel<<<BATCH, 64>>>();
    l1_kernel<<<(BATCH * H1) / 8, 256>>>(W1, b1);
    l2_kernel<<<(BATCH * H2) / 8, 256>>>(W2, b2);
    l3_kernel<<<BATCH, 64>>>(W3, b3, out);
}